// round 11
// baseline (speedup 1.0000x reference)
#include <cuda_runtime.h>
#include <cuda_fp16.h>
#include <math.h>

// ---------------- problem constants ----------------
#define kB   2
#define kSeg 256
#define kT   768          // 3 * kSeg
#define kC   768
#define kH   12
#define kD   64
#define kM   438
#define kV   512
#define kFF  3072
#define kRows (kB * kT)   // 1536

// ---------------- scratch (device globals; no allocs allowed) ----------------
__device__ float  g_x  [kB * kT * kC];
__device__ float  g_h  [kB * kT * kC];
__device__ float  g_y  [kB * kT * kC];
__device__ float  g_qkv[kB * kT * 3 * kC];
__device__ float  g_fc1[kB * kT * kFF];
__device__ float  g_scores[(size_t)kB * kH * kT * kT];
__device__ __half g_probs [(size_t)kB * kH * kT * kT];

// =====================================================================
// Generic fp16 tensor-core GEMM:  C[r][n] = act( scale * sum_k A[r][k]*W[n][k] + bias[n] ) + resid[r][n]
// BT=true  : W element (n,k) is read from W[k*ldb + n]  (transposed-B / NN form)
// AH=true  : A is __half (probs), else float (converted on the fly)
// Batched via blockIdx.z: off = (z/kH)*Z1 + (z%kH)*Z2 per operand.
// Tile: BM=128, BN=64, BK=32; 256 threads = 8 warps (4 x 2), warp tile 32x32,
// mma.sync m16n8k16 f32.f16.f16.f32.
// Mainloop uses register-staged prefetch: next K-tile's global loads are
// issued before the current tile's MMAs, committed to smem afterwards.
// =====================================================================
template<bool BT, bool AH, bool GE>
__global__ __launch_bounds__(256)
void gemm_kernel(const void* __restrict__ Av, const float* __restrict__ W,
                 float* Cout, const float* __restrict__ bias, const float* resid,
                 int Mm, int Nn, int Kk, int lda, int ldb, int ldc,
                 long aZ1, long aZ2, long bZ1, long bZ2, long cZ1, long cZ2,
                 float scale)
{
    __shared__ __half As[128][40];
    __shared__ __half Bs[64][40];

    const int z = blockIdx.z;
    const long offA = (long)(z / kH) * aZ1 + (long)(z % kH) * aZ2;
    const long offB = (long)(z / kH) * bZ1 + (long)(z % kH) * bZ2;
    const long offC = (long)(z / kH) * cZ1 + (long)(z % kH) * cZ2;

    const float*  Af = (const float*)Av;
    const __half* Ah = (const __half*)Av;

    const int tid  = threadIdx.x;
    const int warp = tid >> 5;
    const int lane = tid & 31;
    const int g    = lane >> 2;     // group id (row/col within fragment)
    const int tg   = lane & 3;      // thread in group
    const int wm   = warp & 3;      // 0..3 -> m offset wm*32
    const int wn   = warp >> 2;     // 0..1 -> n offset wn*32
    const int m0   = blockIdx.y * 128;
    const int n0   = blockIdx.x * 64;

    float acc[2][4][4];
#pragma unroll
    for (int a = 0; a < 2; a++)
#pragma unroll
        for (int b = 0; b < 4; b++)
#pragma unroll
            for (int c = 0; c < 4; c++) acc[a][b][c] = 0.f;

    // ---- register staging for the prefetched K-tile ----
    __half2 aReg[8];
    __half2 bRegP[4];   // !BT path (pair loads)
    __half  bRegS[8];   // BT path (scalar loads)

    // load tile at k0 into registers (global -> reg, with f32->f16 convert)
    auto loadTile = [&](int k0) {
#pragma unroll
        for (int i = 0; i < 8; i++) {
            int idx = tid + i * 256;          // 2048 half2-pairs
            int r   = idx >> 4;               // 0..127
            int k2  = idx & 15;               // 0..15
            int kk  = k0 + k2 * 2;
            int gr  = m0 + r;
            __half2 hv;
            if (!AH) {
                float v0 = (gr < Mm && kk     < Kk) ? Af[offA + (long)gr * lda + kk    ] : 0.f;
                float v1 = (gr < Mm && kk + 1 < Kk) ? Af[offA + (long)gr * lda + kk + 1] : 0.f;
                hv = __floats2half2_rn(v0, v1);
            } else {
                if (gr < Mm && kk + 1 < Kk) {
                    hv = *(const __half2*)(Ah + offA + (long)gr * lda + kk);
                } else {
                    __half z0 = __float2half(0.f);
                    __half a0 = (gr < Mm && kk < Kk) ? Ah[offA + (long)gr * lda + kk] : z0;
                    hv = __halves2half2(a0, z0);
                }
            }
            aReg[i] = hv;
        }
        if (!BT) {
#pragma unroll
            for (int i = 0; i < 4; i++) {
                int idx = tid + i * 256;      // 1024 pairs
                int r   = idx >> 4;           // n local 0..63
                int k2  = idx & 15;
                int kk  = k0 + k2 * 2;
                int gn  = n0 + r;
                float v0 = (gn < Nn && kk     < Kk) ? W[offB + (long)gn * ldb + kk    ] : 0.f;
                float v1 = (gn < Nn && kk + 1 < Kk) ? W[offB + (long)gn * ldb + kk + 1] : 0.f;
                bRegP[i] = __floats2half2_rn(v0, v1);
            }
        } else {
#pragma unroll
            for (int i = 0; i < 8; i++) {
                int idx = tid + i * 256;      // 2048 scalars
                int kl  = idx >> 6;           // 0..31
                int nl  = idx & 63;           // 0..63
                int kk  = k0 + kl;
                int gn  = n0 + nl;
                float v = (gn < Nn && kk < Kk) ? W[offB + (long)kk * ldb + gn] : 0.f;
                bRegS[i] = __float2half(v);
            }
        }
    };

    // commit staged registers to shared memory
    auto storeTile = [&]() {
#pragma unroll
        for (int i = 0; i < 8; i++) {
            int idx = tid + i * 256;
            int r   = idx >> 4;
            int k2  = idx & 15;
            *(__half2*)&As[r][k2 * 2] = aReg[i];
        }
        if (!BT) {
#pragma unroll
            for (int i = 0; i < 4; i++) {
                int idx = tid + i * 256;
                int r   = idx >> 4;
                int k2  = idx & 15;
                *(__half2*)&Bs[r][k2 * 2] = bRegP[i];
            }
        } else {
#pragma unroll
            for (int i = 0; i < 8; i++) {
                int idx = tid + i * 256;
                int kl  = idx >> 6;
                int nl  = idx & 63;
                Bs[nl][kl] = bRegS[i];
            }
        }
    };

    // ---- prologue: stage tile 0 ----
    loadTile(0);
    storeTile();
    __syncthreads();

    for (int k0 = 0; k0 < Kk; k0 += 32) {
        const bool hasNext = (k0 + 32 < Kk);
        // issue next tile's global loads before the MMA block (latency overlap)
        if (hasNext) loadTile(k0 + 32);

#pragma unroll
        for (int ks = 0; ks < 32; ks += 16) {
            unsigned a[2][4];
#pragma unroll
            for (int mi = 0; mi < 2; mi++) {
                int rb = wm * 32 + mi * 16;
                a[mi][0] = *(const unsigned*)&As[rb + g    ][ks + tg * 2    ];
                a[mi][1] = *(const unsigned*)&As[rb + g + 8][ks + tg * 2    ];
                a[mi][2] = *(const unsigned*)&As[rb + g    ][ks + tg * 2 + 8];
                a[mi][3] = *(const unsigned*)&As[rb + g + 8][ks + tg * 2 + 8];
            }
#pragma unroll
            for (int ni = 0; ni < 4; ni++) {
                int nb = wn * 32 + ni * 8;
                unsigned b0 = *(const unsigned*)&Bs[nb + g][ks + tg * 2    ];
                unsigned b1 = *(const unsigned*)&Bs[nb + g][ks + tg * 2 + 8];
#pragma unroll
                for (int mi = 0; mi < 2; mi++) {
                    asm volatile(
                        "mma.sync.aligned.m16n8k16.row.col.f32.f16.f16.f32 "
                        "{%0,%1,%2,%3}, {%4,%5,%6,%7}, {%8,%9}, {%0,%1,%2,%3};"
                        : "+f"(acc[mi][ni][0]), "+f"(acc[mi][ni][1]),
                          "+f"(acc[mi][ni][2]), "+f"(acc[mi][ni][3])
                        : "r"(a[mi][0]), "r"(a[mi][1]), "r"(a[mi][2]), "r"(a[mi][3]),
                          "r"(b0), "r"(b1));
                }
            }
        }
        __syncthreads();
        if (hasNext) {
            storeTile();
            __syncthreads();
        }
    }

    // ---- epilogue ----
#pragma unroll
    for (int mi = 0; mi < 2; mi++) {
#pragma unroll
        for (int ni = 0; ni < 4; ni++) {
            int r0 = m0 + wm * 32 + mi * 16 + g;
            int c0 = n0 + wn * 32 + ni * 8 + tg * 2;
#pragma unroll
            for (int e = 0; e < 4; e++) {
                int r = r0 + ((e >> 1) ? 8 : 0);
                int c = c0 + (e & 1);
                if (r < Mm && c < Nn) {
                    float v = acc[mi][ni][e] * scale;
                    if (bias)  v += bias[c];
                    if (GE)    v = 0.5f * v * (1.f + erff(v * 0.70710678118654752f));
                    if (resid) v += resid[offC + (long)r * ldc + c];
                    Cout[offC + (long)r * ldc + c] = v;
                }
            }
        }
    }
}

template<bool BT, bool AH, bool GE>
static void launch_gemm(const void* A, const float* W, float* C,
                        const float* bias, const float* resid,
                        int M, int N, int K, int lda, int ldb, int ldc, int nz,
                        long aZ1, long aZ2, long bZ1, long bZ2, long cZ1, long cZ2,
                        float scale)
{
    dim3 grid((N + 63) / 64, (M + 127) / 128, nz);
    gemm_kernel<BT, AH, GE><<<grid, 256>>>(A, W, C, bias, resid, M, N, K,
                                           lda, ldb, ldc, aZ1, aZ2, bZ1, bZ2, cZ1, cZ2, scale);
}

// ---------------- LayerNorm (one CTA of 256 threads per row of 768) ----------------
__global__ __launch_bounds__(256)
void ln_kernel(const float* __restrict__ x, float* __restrict__ o,
               const float* __restrict__ w, const float* __restrict__ b)
{
    const int row = blockIdx.x;
    const int tid = threadIdx.x;
    const float* xr = x + (long)row * kC;
    __shared__ float r1[256], r2[256];
    float v[3], s = 0.f, s2 = 0.f;
#pragma unroll
    for (int i = 0; i < 3; i++) {
        v[i] = xr[tid + i * 256];
        s += v[i]; s2 += v[i] * v[i];
    }
    r1[tid] = s; r2[tid] = s2;
    __syncthreads();
    for (int off = 128; off > 0; off >>= 1) {
        if (tid < off) { r1[tid] += r1[tid + off]; r2[tid] += r2[tid + off]; }
        __syncthreads();
    }
    float mu  = r1[0] * (1.f / kC);
    float var = r2[0] * (1.f / kC) - mu * mu;
    float inv = rsqrtf(var + 1e-5f);
#pragma unroll
    for (int i = 0; i < 3; i++) {
        int c = tid + i * 256;
        o[(long)row * kC + c] = (v[i] - mu) * inv * w[c] + b[c];
    }
}

// ---------------- embed: x = [condProj | tok_up | tok_down] + pos ----------------
__global__ __launch_bounds__(256)
void embed_kernel(const int* __restrict__ idx_up, const int* __restrict__ idx_down,
                  const float* __restrict__ tok_up, const float* __restrict__ tok_down,
                  const float* __restrict__ pos)
{
    int idx = blockIdx.x * 256 + threadIdx.x;
    if (idx >= kB * kT * kC) return;
    int c   = idx % kC;
    int rem = idx / kC;
    int p   = rem % kT;
    int b   = rem / kT;
    float v;
    if (p < kSeg)            v = g_y[((long)b * kSeg + p) * kC + c];                   // cond projection (temp in g_y)
    else if (p < 2 * kSeg)   v = tok_up[(long)idx_up[b * kSeg + p - kSeg] * kC + c];
    else                     v = tok_down[(long)idx_down[b * kSeg + p - 2 * kSeg] * kC + c];
    g_x[idx] = v + pos[(long)p * kC + c];
}

// ---------------- masked softmax: scores(f32) -> probs(f16), warp per row ----------------
__global__ __launch_bounds__(256)
void softmax_kernel()
{
    const int row  = blockIdx.x * 8 + (threadIdx.x >> 5);   // bh*768 + i
    const int lane = threadIdx.x & 31;
    const float* sr = g_scores + (long)row * kT;
    const int i  = row % kT;
    const int im = i & (kSeg - 1);

    float vals[24];
    float mx = -1e30f;
#pragma unroll
    for (int it = 0; it < 24; it++) {
        int j = lane + it * 32;
        float v = sr[j];
        bool ok = (j & (kSeg - 1)) <= im;
        v = ok ? v : -1e30f;
        vals[it] = v;
        mx = fmaxf(mx, v);
    }
#pragma unroll
    for (int off = 16; off > 0; off >>= 1)
        mx = fmaxf(mx, __shfl_xor_sync(0xffffffffu, mx, off));
    float sum = 0.f;
#pragma unroll
    for (int it = 0; it < 24; it++) {
        float e = (vals[it] > -1e29f) ? expf(vals[it] - mx) : 0.f;
        vals[it] = e;
        sum += e;
    }
#pragma unroll
    for (int off = 16; off > 0; off >>= 1)
        sum += __shfl_xor_sync(0xffffffffu, sum, off);
    float inv = 1.f / sum;
#pragma unroll
    for (int it = 0; it < 24; it++) {
        int j = lane + it * 32;
        g_probs[(long)row * kT + j] = __float2half(vals[it] * inv);
    }
}

// =====================================================================
// metadata.txt input order (setup_inputs() dict insertion order):
//   0 idx_up, 1 idx_down, 2 cond, 3 tok_up, 4 tok_down, 5 pos_emb,
//   6 cond_w, 7 cond_b, 8 lnf_w, 9 lnf_b, 10 head_up_w, 11 head_down_w,
//   12..21 base_{ln1,ln2,qkv_w,qkv_b,proj_w,proj_b,fc1_w,fc1_b,fc2_w,fc2_b},
//   22..31 head_{same}
// =====================================================================
extern "C" void kernel_launch(void* const* d_in, const int* in_sizes, int n_in,
                              void* d_out, int out_size)
{
    (void)in_sizes; (void)n_in; (void)out_size;
    const int*   idx_up   = (const int*)d_in[0];
    const int*   idx_down = (const int*)d_in[1];
    const float* cond     = (const float*)d_in[2];
    const float* tok_up   = (const float*)d_in[3];
    const float* tok_down = (const float*)d_in[4];
    const float* pos_emb  = (const float*)d_in[5];
    const float* cond_w   = (const float*)d_in[6];
    const float* cond_b   = (const float*)d_in[7];
    const float* lnf_w    = (const float*)d_in[8];
    const float* lnf_b    = (const float*)d_in[9];
    const float* head_up_w   = (const float*)d_in[10];
    const float* head_down_w = (const float*)d_in[11];

    float *x, *h, *y, *qkv, *fc1, *scores; __half* probs;
    cudaGetSymbolAddress((void**)&x,      g_x);
    cudaGetSymbolAddress((void**)&h,      g_h);
    cudaGetSymbolAddress((void**)&y,      g_y);
    cudaGetSymbolAddress((void**)&qkv,    g_qkv);
    cudaGetSymbolAddress((void**)&fc1,    g_fc1);
    cudaGetSymbolAddress((void**)&scores, g_scores);
    cudaGetSymbolAddress((void**)&probs,  g_probs);

    float* out = (float*)d_out;

    // ---- embed: cond projection (temp into g_y), then gather + pos ----
    launch_gemm<false,false,false>(cond, cond_w, y, cond_b, nullptr,
        kB * kSeg, kC, kM, kM, kM, kC, 1, 0,0,0,0,0,0, 1.f);
    embed_kernel<<<(kB * kT * kC + 255) / 256, 256>>>(idx_up, idx_down, tok_up, tok_down, pos_emb);

    // ---- 2 stacks x 6 blocks ----
    for (int s = 0; s < 2; s++) {
        const int base = 12 + 10 * s;                    // 12 = base stack, 22 = head stack
        const float* ln1  = (const float*)d_in[base + 0];
        const float* ln2  = (const float*)d_in[base + 1];
        const float* qkvw = (const float*)d_in[base + 2];
        const float* qkvb = (const float*)d_in[base + 3];
        const float* pw   = (const float*)d_in[base + 4];
        const float* pb   = (const float*)d_in[base + 5];
        const float* f1w  = (const float*)d_in[base + 6];
        const float* f1b  = (const float*)d_in[base + 7];
        const float* f2w  = (const float*)d_in[base + 8];
        const float* f2b  = (const float*)d_in[base + 9];
        for (int l = 0; l < 6; l++) {
            // ln1
            ln_kernel<<<kRows, 256>>>(x, h, ln1 + (long)l * 2 * kC, ln1 + (long)l * 2 * kC + kC);
            // qkv projection [1536,768] x [2304,768]^T
            launch_gemm<false,false,false>(h, qkvw + (long)l * 3 * kC * kC, qkv,
                qkvb + (long)l * 3 * kC, nullptr,
                kRows, 3 * kC, kC, kC, kC, 3 * kC, 1, 0,0,0,0,0,0, 1.f);
            // scores = q k^T * 1/8  (batched over 24 (b,h))
            launch_gemm<false,false,false>(qkv, qkv + kC, scores, nullptr, nullptr,
                kT, kT, kD, 3 * kC, 3 * kC, kT, kB * kH,
                (long)kT * 3 * kC, 64, (long)kT * 3 * kC, 64,
                (long)kH * kT * kT, (long)kT * kT, 0.125f);
            // masked softmax -> fp16 probs
            softmax_kernel<<<kB * kH * kT / 8, 256>>>();
            // y = probs @ V (batched, B-transposed, A half)
            launch_gemm<true,true,false>(probs, qkv + 2 * kC, y, nullptr, nullptr,
                kT, kD, kT, kT, 3 * kC, kC, kB * kH,
                (long)kH * kT * kT, (long)kT * kT, (long)kT * 3 * kC, 64,
                (long)kT * kC, 64, 1.f);
            // x = x + proj(y)
            launch_gemm<false,false,false>(y, pw + (long)l * kC * kC, x,
                pb + (long)l * kC, x, kRows, kC, kC, kC, kC, kC, 1, 0,0,0,0,0,0, 1.f);
            // ln2
            ln_kernel<<<kRows, 256>>>(x, h, ln2 + (long)l * 2 * kC, ln2 + (long)l * 2 * kC + kC);
            // fc1 + exact GELU
            launch_gemm<false,false,true>(h, f1w + (long)l * kFF * kC, fc1,
                f1b + (long)l * kFF, nullptr,
                kRows, kFF, kC, kC, kC, kFF, 1, 0,0,0,0,0,0, 1.f);
            // x = x + fc2(gelu)
            launch_gemm<false,false,false>(fc1, f2w + (long)l * kC * kFF, x,
                f2b + (long)l * kC, x, kRows, kC, kFF, kFF, kFF, kC, 1, 0,0,0,0,0,0, 1.f);
        }
    }

    // ---- final LN + heads ----
    ln_kernel<<<kRows, 256>>>(x, h, lnf_w, lnf_b);
    for (int b = 0; b < kB; b++) {
        // logits_up: rows [t, 2t)
        launch_gemm<false,false,false>(h + ((long)b * kT + kSeg) * kC, head_up_w,
            out + (long)b * kSeg * kV, nullptr, nullptr,
            kSeg, kV, kC, kC, kC, kV, 1, 0,0,0,0,0,0, 1.f);
        // logits_down: rows [2t, 3t)
        launch_gemm<false,false,false>(h + ((long)b * kT + 2 * kSeg) * kC, head_down_w,
            out + ((long)kB + b) * kSeg * kV, nullptr, nullptr,
            kSeg, kV, kC, kC, kC, kV, 1, 0,0,0,0,0,0, 1.f);
    }
}

// round 14
// speedup vs baseline: 1.0296x; 1.0296x over previous
#include <cuda_runtime.h>
#include <cuda_fp16.h>
#include <math.h>

// ---------------- problem constants ----------------
#define kB   2
#define kSeg 256
#define kT   768          // 3 * kSeg
#define kC   768
#define kH   12
#define kD   64
#define kM   438
#define kV   512
#define kFF  3072
#define kRows (kB * kT)   // 1536

// ---------------- scratch (device globals; no allocs allowed) ----------------
__device__ float  g_x  [kB * kT * kC];
__device__ float  g_h  [kB * kT * kC];
__device__ float  g_y  [kB * kT * kC];
__device__ float  g_qkv[kB * kT * 3 * kC];
__device__ float  g_fc1[kB * kT * kFF];
__device__ float  g_scores[(size_t)kB * kH * kT * kT];
__device__ __half g_probs [(size_t)kB * kH * kT * kT];

// =====================================================================
// Generic fp16 tensor-core GEMM with ldmatrix fragment loads and
// ping-pong double-buffered smem (single __syncthreads per K-tile).
// C[r][n] = act( scale * sum_k A[r][k]*W[n][k] + bias[n] ) + resid[r][n]
// BT: W read transposed (W[k*ldb+n]); AH: A is __half; GE: exact GELU.
// Tile BM=128, BN=64, BK=32; 256 threads = 8 warps (4x2), warp tile 32x32,
// mma.sync m16n8k16 f32.f16.f16.f32. Values identical to R11 kernel.
// =====================================================================
template<bool BT, bool AH, bool GE>
__global__ __launch_bounds__(256)
void gemm_kernel(const void* __restrict__ Av, const float* __restrict__ W,
                 float* Cout, const float* __restrict__ bias, const float* resid,
                 int Mm, int Nn, int Kk, int lda, int ldb, int ldc,
                 long aZ1, long aZ2, long bZ1, long bZ2, long cZ1, long cZ2,
                 float scale)
{
    __shared__ __align__(16) __half As[2][128][40];
    __shared__ __align__(16) __half Bs[2][64][40];

    const int z = blockIdx.z;
    const long offA = (long)(z / kH) * aZ1 + (long)(z % kH) * aZ2;
    const long offB = (long)(z / kH) * bZ1 + (long)(z % kH) * bZ2;
    const long offC = (long)(z / kH) * cZ1 + (long)(z % kH) * cZ2;

    const float*  Af = (const float*)Av;
    const __half* Ah = (const __half*)Av;

    const int tid  = threadIdx.x;
    const int warp = tid >> 5;
    const int lane = tid & 31;
    const int g    = lane >> 2;
    const int tg   = lane & 3;
    const int wm   = warp & 3;      // m offset wm*32
    const int wn   = warp >> 2;     // n offset wn*32
    const int m0   = blockIdx.y * 128;
    const int n0   = blockIdx.x * 64;

    float acc[2][4][4];
#pragma unroll
    for (int a = 0; a < 2; a++)
#pragma unroll
        for (int b = 0; b < 4; b++)
#pragma unroll
            for (int c = 0; c < 4; c++) acc[a][b][c] = 0.f;

    // ---- register staging for the prefetched K-tile ----
    __half2 aReg[8];
    __half2 bRegP[4];
    __half  bRegS[8];

    auto loadTile = [&](int k0) {
#pragma unroll
        for (int i = 0; i < 8; i++) {
            int idx = tid + i * 256;
            int r   = idx >> 4;
            int k2  = idx & 15;
            int kk  = k0 + k2 * 2;
            int gr  = m0 + r;
            __half2 hv;
            if (!AH) {
                float v0 = (gr < Mm && kk     < Kk) ? Af[offA + (long)gr * lda + kk    ] : 0.f;
                float v1 = (gr < Mm && kk + 1 < Kk) ? Af[offA + (long)gr * lda + kk + 1] : 0.f;
                hv = __floats2half2_rn(v0, v1);
            } else {
                if (gr < Mm && kk + 1 < Kk) {
                    hv = *(const __half2*)(Ah + offA + (long)gr * lda + kk);
                } else {
                    __half z0 = __float2half(0.f);
                    __half a0 = (gr < Mm && kk < Kk) ? Ah[offA + (long)gr * lda + kk] : z0;
                    hv = __halves2half2(a0, z0);
                }
            }
            aReg[i] = hv;
        }
        if (!BT) {
#pragma unroll
            for (int i = 0; i < 4; i++) {
                int idx = tid + i * 256;
                int r   = idx >> 4;
                int k2  = idx & 15;
                int kk  = k0 + k2 * 2;
                int gn  = n0 + r;
                float v0 = (gn < Nn && kk     < Kk) ? W[offB + (long)gn * ldb + kk    ] : 0.f;
                float v1 = (gn < Nn && kk + 1 < Kk) ? W[offB + (long)gn * ldb + kk + 1] : 0.f;
                bRegP[i] = __floats2half2_rn(v0, v1);
            }
        } else {
#pragma unroll
            for (int i = 0; i < 8; i++) {
                int idx = tid + i * 256;
                int kl  = idx >> 6;
                int nl  = idx & 63;
                int kk  = k0 + kl;
                int gn  = n0 + nl;
                float v = (gn < Nn && kk < Kk) ? W[offB + (long)kk * ldb + gn] : 0.f;
                bRegS[i] = __float2half(v);
            }
        }
    };

    auto storeTile = [&](int buf) {
#pragma unroll
        for (int i = 0; i < 8; i++) {
            int idx = tid + i * 256;
            int r   = idx >> 4;
            int k2  = idx & 15;
            *(__half2*)&As[buf][r][k2 * 2] = aReg[i];
        }
        if (!BT) {
#pragma unroll
            for (int i = 0; i < 4; i++) {
                int idx = tid + i * 256;
                int r   = idx >> 4;
                int k2  = idx & 15;
                *(__half2*)&Bs[buf][r][k2 * 2] = bRegP[i];
            }
        } else {
#pragma unroll
            for (int i = 0; i < 8; i++) {
                int idx = tid + i * 256;
                int kl  = idx >> 6;
                int nl  = idx & 63;
                Bs[buf][nl][kl] = bRegS[i];
            }
        }
    };

    // smem base addresses (32-bit shared space) for ldmatrix
    const unsigned aBase0 = (unsigned)__cvta_generic_to_shared(&As[0][0][0]);
    const unsigned aBase1 = (unsigned)__cvta_generic_to_shared(&As[1][0][0]);
    const unsigned bBase0 = (unsigned)__cvta_generic_to_shared(&Bs[0][0][0]);
    const unsigned bBase1 = (unsigned)__cvta_generic_to_shared(&Bs[1][0][0]);

    // lane-dependent ldmatrix offsets (in elements)
    const int aRowOff = lane & 15;            // row within 16-row group
    const int aColSel = (lane >> 4) * 8;      // k half: 0 or 8
    const int bRowOff = (lane & 7) + ((lane >> 4) << 3);   // n row
    const int bColSel = ((lane >> 3) & 1) * 8;             // k half

    auto computeTile = [&](int buf) {
        const unsigned aB = buf ? aBase1 : aBase0;
        const unsigned bB = buf ? bBase1 : bBase0;
#pragma unroll
        for (int ks = 0; ks < 32; ks += 16) {
            unsigned a[2][4];
#pragma unroll
            for (int mi = 0; mi < 2; mi++) {
                int rb = wm * 32 + mi * 16;
                unsigned addr = aB + (unsigned)(((rb + aRowOff) * 40 + ks + aColSel) * 2);
                asm volatile(
                    "ldmatrix.sync.aligned.m8n8.x4.shared.b16 {%0,%1,%2,%3}, [%4];"
                    : "=r"(a[mi][0]), "=r"(a[mi][1]), "=r"(a[mi][2]), "=r"(a[mi][3])
                    : "r"(addr));
            }
            unsigned bf[4][2];
#pragma unroll
            for (int nn = 0; nn < 2; nn++) {
                int nb = wn * 32 + nn * 16;
                unsigned addr = bB + (unsigned)(((nb + bRowOff) * 40 + ks + bColSel) * 2);
                unsigned r0, r1, r2, r3;
                asm volatile(
                    "ldmatrix.sync.aligned.m8n8.x4.shared.b16 {%0,%1,%2,%3}, [%4];"
                    : "=r"(r0), "=r"(r1), "=r"(r2), "=r"(r3)
                    : "r"(addr));
                bf[nn * 2    ][0] = r0; bf[nn * 2    ][1] = r1;
                bf[nn * 2 + 1][0] = r2; bf[nn * 2 + 1][1] = r3;
            }
#pragma unroll
            for (int ni = 0; ni < 4; ni++) {
#pragma unroll
                for (int mi = 0; mi < 2; mi++) {
                    asm volatile(
                        "mma.sync.aligned.m16n8k16.row.col.f32.f16.f16.f32 "
                        "{%0,%1,%2,%3}, {%4,%5,%6,%7}, {%8,%9}, {%0,%1,%2,%3};"
                        : "+f"(acc[mi][ni][0]), "+f"(acc[mi][ni][1]),
                          "+f"(acc[mi][ni][2]), "+f"(acc[mi][ni][3])
                        : "r"(a[mi][0]), "r"(a[mi][1]), "r"(a[mi][2]), "r"(a[mi][3]),
                          "r"(bf[ni][0]), "r"(bf[ni][1]));
                }
            }
        }
    };

    // ---- pipelined mainloop: one sync per K-tile ----
    const int nK = (Kk + 31) / 32;
    loadTile(0);
    storeTile(0);
    __syncthreads();
    for (int kt = 0; kt < nK; kt++) {
        const bool hasNext = (kt + 1 < nK);
        if (hasNext) loadTile((kt + 1) * 32);   // global -> regs (overlaps MMA)
        computeTile(kt & 1);
        if (hasNext) storeTile((kt + 1) & 1);   // regs -> other smem buffer
        __syncthreads();
    }

    // ---- epilogue ----
#pragma unroll
    for (int mi = 0; mi < 2; mi++) {
#pragma unroll
        for (int ni = 0; ni < 4; ni++) {
            int r0 = m0 + wm * 32 + mi * 16 + g;
            int c0 = n0 + wn * 32 + ni * 8 + tg * 2;
#pragma unroll
            for (int e = 0; e < 4; e++) {
                int r = r0 + ((e >> 1) ? 8 : 0);
                int c = c0 + (e & 1);
                if (r < Mm && c < Nn) {
                    float v = acc[mi][ni][e] * scale;
                    if (bias)  v += bias[c];
                    if (GE)    v = 0.5f * v * (1.f + erff(v * 0.70710678118654752f));
                    if (resid) v += resid[offC + (long)r * ldc + c];
                    Cout[offC + (long)r * ldc + c] = v;
                }
            }
        }
    }
}

template<bool BT, bool AH, bool GE>
static void launch_gemm(const void* A, const float* W, float* C,
                        const float* bias, const float* resid,
                        int M, int N, int K, int lda, int ldb, int ldc, int nz,
                        long aZ1, long aZ2, long bZ1, long bZ2, long cZ1, long cZ2,
                        float scale)
{
    dim3 grid((N + 63) / 64, (M + 127) / 128, nz);
    gemm_kernel<BT, AH, GE><<<grid, 256>>>(A, W, C, bias, resid, M, N, K,
                                           lda, ldb, ldc, aZ1, aZ2, bZ1, bZ2, cZ1, cZ2, scale);
}

// ---------------- LayerNorm (one CTA of 256 threads per row of 768) ----------------
__global__ __launch_bounds__(256)
void ln_kernel(const float* __restrict__ x, float* __restrict__ o,
               const float* __restrict__ w, const float* __restrict__ b)
{
    const int row = blockIdx.x;
    const int tid = threadIdx.x;
    const float* xr = x + (long)row * kC;
    __shared__ float r1[256], r2[256];
    float v[3], s = 0.f, s2 = 0.f;
#pragma unroll
    for (int i = 0; i < 3; i++) {
        v[i] = xr[tid + i * 256];
        s += v[i]; s2 += v[i] * v[i];
    }
    r1[tid] = s; r2[tid] = s2;
    __syncthreads();
    for (int off = 128; off > 0; off >>= 1) {
        if (tid < off) { r1[tid] += r1[tid + off]; r2[tid] += r2[tid + off]; }
        __syncthreads();
    }
    float mu  = r1[0] * (1.f / kC);
    float var = r2[0] * (1.f / kC) - mu * mu;
    float inv = rsqrtf(var + 1e-5f);
#pragma unroll
    for (int i = 0; i < 3; i++) {
        int c = tid + i * 256;
        o[(long)row * kC + c] = (v[i] - mu) * inv * w[c] + b[c];
    }
}

// ---------------- embed: x = [condProj | tok_up | tok_down] + pos ----------------
__global__ __launch_bounds__(256)
void embed_kernel(const int* __restrict__ idx_up, const int* __restrict__ idx_down,
                  const float* __restrict__ tok_up, const float* __restrict__ tok_down,
                  const float* __restrict__ pos)
{
    int idx = blockIdx.x * 256 + threadIdx.x;
    if (idx >= kB * kT * kC) return;
    int c   = idx % kC;
    int rem = idx / kC;
    int p   = rem % kT;
    int b   = rem / kT;
    float v;
    if (p < kSeg)            v = g_y[((long)b * kSeg + p) * kC + c];
    else if (p < 2 * kSeg)   v = tok_up[(long)idx_up[b * kSeg + p - kSeg] * kC + c];
    else                     v = tok_down[(long)idx_down[b * kSeg + p - 2 * kSeg] * kC + c];
    g_x[idx] = v + pos[(long)p * kC + c];
}

// ---------------- masked softmax: scores(f32) -> probs(f16), warp per row ----------------
__global__ __launch_bounds__(256)
void softmax_kernel()
{
    const int row  = blockIdx.x * 8 + (threadIdx.x >> 5);
    const int lane = threadIdx.x & 31;
    const float* sr = g_scores + (long)row * kT;
    const int i  = row % kT;
    const int im = i & (kSeg - 1);

    float vals[24];
    float mx = -1e30f;
#pragma unroll
    for (int it = 0; it < 24; it++) {
        int j = lane + it * 32;
        float v = sr[j];
        bool ok = (j & (kSeg - 1)) <= im;
        v = ok ? v : -1e30f;
        vals[it] = v;
        mx = fmaxf(mx, v);
    }
#pragma unroll
    for (int off = 16; off > 0; off >>= 1)
        mx = fmaxf(mx, __shfl_xor_sync(0xffffffffu, mx, off));
    float sum = 0.f;
#pragma unroll
    for (int it = 0; it < 24; it++) {
        float e = (vals[it] > -1e29f) ? expf(vals[it] - mx) : 0.f;
        vals[it] = e;
        sum += e;
    }
#pragma unroll
    for (int off = 16; off > 0; off >>= 1)
        sum += __shfl_xor_sync(0xffffffffu, sum, off);
    float inv = 1.f / sum;
#pragma unroll
    for (int it = 0; it < 24; it++) {
        int j = lane + it * 32;
        g_probs[(long)row * kT + j] = __float2half(vals[it] * inv);
    }
}

// =====================================================================
// metadata.txt input order (setup_inputs() dict insertion order):
//   0 idx_up, 1 idx_down, 2 cond, 3 tok_up, 4 tok_down, 5 pos_emb,
//   6 cond_w, 7 cond_b, 8 lnf_w, 9 lnf_b, 10 head_up_w, 11 head_down_w,
//   12..21 base_{ln1,ln2,qkv_w,qkv_b,proj_w,proj_b,fc1_w,fc1_b,fc2_w,fc2_b},
//   22..31 head_{same}
// =====================================================================
extern "C" void kernel_launch(void* const* d_in, const int* in_sizes, int n_in,
                              void* d_out, int out_size)
{
    (void)in_sizes; (void)n_in; (void)out_size;
    const int*   idx_up   = (const int*)d_in[0];
    const int*   idx_down = (const int*)d_in[1];
    const float* cond     = (const float*)d_in[2];
    const float* tok_up   = (const float*)d_in[3];
    const float* tok_down = (const float*)d_in[4];
    const float* pos_emb  = (const float*)d_in[5];
    const float* cond_w   = (const float*)d_in[6];
    const float* cond_b   = (const float*)d_in[7];
    const float* lnf_w    = (const float*)d_in[8];
    const float* lnf_b    = (const float*)d_in[9];
    const float* head_up_w   = (const float*)d_in[10];
    const float* head_down_w = (const float*)d_in[11];

    float *x, *h, *y, *qkv, *fc1, *scores; __half* probs;
    cudaGetSymbolAddress((void**)&x,      g_x);
    cudaGetSymbolAddress((void**)&h,      g_h);
    cudaGetSymbolAddress((void**)&y,      g_y);
    cudaGetSymbolAddress((void**)&qkv,    g_qkv);
    cudaGetSymbolAddress((void**)&fc1,    g_fc1);
    cudaGetSymbolAddress((void**)&scores, g_scores);
    cudaGetSymbolAddress((void**)&probs,  g_probs);

    float* out = (float*)d_out;

    // ---- embed: cond projection (temp into g_y), then gather + pos ----
    launch_gemm<false,false,false>(cond, cond_w, y, cond_b, nullptr,
        kB * kSeg, kC, kM, kM, kM, kC, 1, 0,0,0,0,0,0, 1.f);
    embed_kernel<<<(kB * kT * kC + 255) / 256, 256>>>(idx_up, idx_down, tok_up, tok_down, pos_emb);

    // ---- 2 stacks x 6 blocks ----
    for (int s = 0; s < 2; s++) {
        const int base = 12 + 10 * s;
        const float* ln1  = (const float*)d_in[base + 0];
        const float* ln2  = (const float*)d_in[base + 1];
        const float* qkvw = (const float*)d_in[base + 2];
        const float* qkvb = (const float*)d_in[base + 3];
        const float* pw   = (const float*)d_in[base + 4];
        const float* pb   = (const float*)d_in[base + 5];
        const float* f1w  = (const float*)d_in[base + 6];
        const float* f1b  = (const float*)d_in[base + 7];
        const float* f2w  = (const float*)d_in[base + 8];
        const float* f2b  = (const float*)d_in[base + 9];
        for (int l = 0; l < 6; l++) {
            // ln1
            ln_kernel<<<kRows, 256>>>(x, h, ln1 + (long)l * 2 * kC, ln1 + (long)l * 2 * kC + kC);
            // qkv projection [1536,768] x [2304,768]^T
            launch_gemm<false,false,false>(h, qkvw + (long)l * 3 * kC * kC, qkv,
                qkvb + (long)l * 3 * kC, nullptr,
                kRows, 3 * kC, kC, kC, kC, 3 * kC, 1, 0,0,0,0,0,0, 1.f);
            // scores = q k^T * 1/8  (batched over 24 (b,h))
            launch_gemm<false,false,false>(qkv, qkv + kC, scores, nullptr, nullptr,
                kT, kT, kD, 3 * kC, 3 * kC, kT, kB * kH,
                (long)kT * 3 * kC, 64, (long)kT * 3 * kC, 64,
                (long)kH * kT * kT, (long)kT * kT, 0.125f);
            // masked softmax -> fp16 probs
            softmax_kernel<<<kB * kH * kT / 8, 256>>>();
            // y = probs @ V (batched, B-transposed, A half)
            launch_gemm<true,true,false>(probs, qkv + 2 * kC, y, nullptr, nullptr,
                kT, kD, kT, kT, 3 * kC, kC, kB * kH,
                (long)kH * kT * kT, (long)kT * kT, (long)kT * 3 * kC, 64,
                (long)kT * kC, 64, 1.f);
            // x = x + proj(y)
            launch_gemm<false,false,false>(y, pw + (long)l * kC * kC, x,
                pb + (long)l * kC, x, kRows, kC, kC, kC, kC, kC, 1, 0,0,0,0,0,0, 1.f);
            // ln2
            ln_kernel<<<kRows, 256>>>(x, h, ln2 + (long)l * 2 * kC, ln2 + (long)l * 2 * kC + kC);
            // fc1 + exact GELU
            launch_gemm<false,false,true>(h, f1w + (long)l * kFF * kC, fc1,
                f1b + (long)l * kFF, nullptr,
                kRows, kFF, kC, kC, kC, kFF, 1, 0,0,0,0,0,0, 1.f);
            // x = x + fc2(gelu)
            launch_gemm<false,false,false>(fc1, f2w + (long)l * kC * kFF, x,
                f2b + (long)l * kC, x, kRows, kC, kFF, kFF, kFF, kC, 1, 0,0,0,0,0,0, 1.f);
        }
    }

    // ---- final LN + heads ----
    ln_kernel<<<kRows, 256>>>(x, h, lnf_w, lnf_b);
    for (int b = 0; b < kB; b++) {
        launch_gemm<false,false,false>(h + ((long)b * kT + kSeg) * kC, head_up_w,
            out + (long)b * kSeg * kV, nullptr, nullptr,
            kSeg, kV, kC, kC, kC, kV, 1, 0,0,0,0,0,0, 1.f);
        launch_gemm<false,false,false>(h + ((long)b * kT + 2 * kSeg) * kC, head_down_w,
            out + ((long)kB + b) * kSeg * kV, nullptr, nullptr,
            kSeg, kV, kC, kC, kC, kV, 1, 0,0,0,0,0,0, 1.f);
    }
}